// round 8
// baseline (speedup 1.0000x reference)
#include <cuda_runtime.h>
#include <cuda_bf16.h>
#include <cstdint>

// ============================================================================
// SelfAttention via mma.sync (HMMA) bf16 hi/lo-split GEMMs, 3 passes ≈ fp32.
// R8 = R5 resubmit (previous round was an infra failure, kernel unmeasured):
// R3 tiling (128x128, warp 64x32, 2 CTA/SM) + accumulator-RAW-chain fix:
//     the 3 split passes sweep ALL 16 acc quads before any acc is reused.
// B=4, L=2048, D=1024.
// ============================================================================

#define BATCH 4
#define LSEQ  2048
#define DDIM  1024

#define BM 128
#define BN 128
#define BK 32

// ---- scratch ---------------------------------------------------------------
__device__ __nv_bfloat16 g_xh[8388608],  g_xl[8388608];
__device__ __nv_bfloat16 g_w1h[1048576], g_w1l[1048576];
__device__ __nv_bfloat16 g_w2h[1048576], g_w2l[1048576];
__device__ __nv_bfloat16 g_qh[8388608],  g_ql[8388608];
__device__ __nv_bfloat16 g_vh[8388608],  g_vl[8388608];
__device__ __nv_bfloat16 g_vth[8388608], g_vtl[8388608];
__device__ float         g_S[16777216];
__device__ __nv_bfloat16 g_ph[16777216], g_pl[16777216];

// ---- helpers ---------------------------------------------------------------
__device__ __forceinline__ uint32_t smem_u32(const void* p) {
    uint32_t a;
    asm("{ .reg .u64 t; cvta.to.shared.u64 t, %1; cvt.u32.u64 %0, t; }" : "=r"(a) : "l"(p));
    return a;
}
__device__ __forceinline__ void cp16(uint32_t dst, const void* src) {
    asm volatile("cp.async.cg.shared.global [%0], [%1], 16;" :: "r"(dst), "l"(src));
}
__device__ __forceinline__ void cp_commit() { asm volatile("cp.async.commit_group;" ::: "memory"); }
#define CP_WAIT1 asm volatile("cp.async.wait_group 1;" ::: "memory")
#define CP_WAIT0 asm volatile("cp.async.wait_group 0;" ::: "memory")

__device__ __forceinline__ void ldsm4(uint32_t& r0, uint32_t& r1, uint32_t& r2, uint32_t& r3,
                                      uint32_t addr) {
    asm volatile("ldmatrix.sync.aligned.m8n8.x4.shared.b16 {%0,%1,%2,%3}, [%4];"
                 : "=r"(r0), "=r"(r1), "=r"(r2), "=r"(r3) : "r"(addr));
}
__device__ __forceinline__ void mma16816(float* c, const uint32_t* a, const uint32_t* b) {
    asm volatile(
        "mma.sync.aligned.m16n8k16.row.col.f32.bf16.bf16.f32 "
        "{%0,%1,%2,%3}, {%4,%5,%6,%7}, {%8,%9}, {%0,%1,%2,%3};"
        : "+f"(c[0]), "+f"(c[1]), "+f"(c[2]), "+f"(c[3])
        : "r"(a[0]), "r"(a[1]), "r"(a[2]), "r"(a[3]), "r"(b[0]), "r"(b[1]));
}
__device__ __forceinline__ uint32_t pk2(float a, float b) {
    __nv_bfloat162 t = __floats2bfloat162_rn(a, b);
    return *reinterpret_cast<uint32_t*>(&t);
}

// SMEM layout (bytes): 4 tiles of 128 rows x 80 B = 10240 B each
#define T_AH 0
#define T_AL 10240
#define T_BH 20480
#define T_BL 30720
#define STAGE 40960
#define SMEM_TOTAL (2 * STAGE)    // 81920

// ============================================================================
// C[M,N] = A[M,K] * B[N,K]^T  (both K-contiguous), hi/lo split, 3 MMA passes.
// grid (N/BN, M/BM, batch), 256 threads (8 warps, warp tile 64x32).
// ============================================================================
template <bool BIAS, bool BF16OUT>
__global__ __launch_bounds__(256, 2) void gemm_hmma(
    const __nv_bfloat16* __restrict__ Ah, const __nv_bfloat16* __restrict__ Al,
    const __nv_bfloat16* __restrict__ Bh, const __nv_bfloat16* __restrict__ Bl,
    const float* __restrict__ bias,
    float* __restrict__ Cf, __nv_bfloat16* __restrict__ Ch, __nv_bfloat16* __restrict__ Cl,
    int K, int lda, int ldb, int ldc,
    long long sA, long long sB, long long sC)
{
    extern __shared__ char smem[];
    const uint32_t sb = smem_u32(smem);

    const int tid = threadIdx.x, wid = tid >> 5, lane = tid & 31;
    const int wy = wid >> 2, wx = wid & 3;           // warp grid 2 x 4
    const int m0 = blockIdx.y * BM, n0 = blockIdx.x * BN;
    const long long z = blockIdx.z;
    Ah += z * sA; Al += z * sA; Bh += z * sB; Bl += z * sB;
    if (BF16OUT) { Ch += z * sC; Cl += z * sC; } else { Cf += z * sC; }

    // global->smem mapping: 512 16B segs per tile (128 rows x 4)
    const int grow = tid >> 2;
    const int gseg = tid & 3;

    float acc[4][4][4];
#pragma unroll
    for (int i = 0; i < 4; ++i)
#pragma unroll
        for (int j = 0; j < 4; ++j)
#pragma unroll
            for (int e = 0; e < 4; ++e) acc[i][j][e] = 0.f;

    const int nk = K / BK;

    auto load_chunk = [&](int t, int b) {
        const uint32_t st = sb + b * STAGE;
        const int k0 = t * BK;
#pragma unroll
        for (int h = 0; h < 2; ++h) {
            const int row = grow + h * 64;
            const uint32_t d = (uint32_t)(row * 80 + gseg * 16);
            const size_t ga = (size_t)(m0 + row) * lda + k0 + gseg * 8;
            const size_t gb = (size_t)(n0 + row) * ldb + k0 + gseg * 8;
            cp16(st + T_AH + d, Ah + ga);
            cp16(st + T_AL + d, Al + ga);
            cp16(st + T_BH + d, Bh + gb);
            cp16(st + T_BL + d, Bl + gb);
        }
    };

    load_chunk(0, 0);
    cp_commit();

    for (int t = 0; t < nk; ++t) {
        const int buf = t & 1;
        if (t + 1 < nk) { load_chunk(t + 1, buf ^ 1); cp_commit(); CP_WAIT1; }
        else            { CP_WAIT0; }
        __syncthreads();

        const uint32_t st = sb + buf * STAGE;
        const int lr = lane & 15, lc = lane >> 4;
#pragma unroll
        for (int ks = 0; ks < 2; ++ks) {
            const uint32_t acol = (uint32_t)(ks * 32 + lc * 16);
            const uint32_t ab = st + T_AH + (uint32_t)((wy * 64 + lr) * 80) + acol;
            const uint32_t bb = st + T_BH + (uint32_t)((wx * 32 + lr) * 80) + acol;

            uint32_t ah[4][4], al[4][4], bh[4][2], bl[4][2];
#pragma unroll
            for (int i = 0; i < 4; ++i) {
                const uint32_t ad = ab + (uint32_t)(i * 16 * 80);
                ldsm4(ah[i][0], ah[i][1], ah[i][2], ah[i][3], ad);
                ldsm4(al[i][0], al[i][1], al[i][2], al[i][3], ad + (T_AL - T_AH));
            }
#pragma unroll
            for (int j = 0; j < 2; ++j) {
                const uint32_t bd = bb + (uint32_t)(j * 16 * 80);
                uint32_t r0, r1, r2, r3;
                ldsm4(r0, r1, r2, r3, bd);
                bh[2*j][0] = r0; bh[2*j][1] = r2; bh[2*j+1][0] = r1; bh[2*j+1][1] = r3;
                ldsm4(r0, r1, r2, r3, bd + (T_BL - T_BH));
                bl[2*j][0] = r0; bl[2*j][1] = r2; bl[2*j+1][0] = r1; bl[2*j+1][1] = r3;
            }
            // --- 3 passes, each sweeping all 16 acc quads: RAW distance = 16 ---
#pragma unroll
            for (int i = 0; i < 4; ++i)
#pragma unroll
                for (int j = 0; j < 4; ++j)
                    mma16816(acc[i][j], ah[i], bh[j]);
#pragma unroll
            for (int i = 0; i < 4; ++i)
#pragma unroll
                for (int j = 0; j < 4; ++j)
                    mma16816(acc[i][j], ah[i], bl[j]);
#pragma unroll
            for (int i = 0; i < 4; ++i)
#pragma unroll
                for (int j = 0; j < 4; ++j)
                    mma16816(acc[i][j], al[i], bh[j]);
        }
        __syncthreads();
    }

    // ---- epilogue ----
    const int rbase = m0 + wy * 64 + (lane >> 2);
    const int cbase = n0 + wx * 32 + (lane & 3) * 2;
#pragma unroll
    for (int j = 0; j < 4; ++j) {
        const int col = cbase + j * 8;
        float b0 = 0.f, b1 = 0.f;
        if (BIAS) { b0 = __ldg(&bias[col]); b1 = __ldg(&bias[col + 1]); }
#pragma unroll
        for (int i = 0; i < 4; ++i) {
            const int row = rbase + i * 16;
            float v0 = acc[i][j][0] + b0, v1 = acc[i][j][1] + b1;
            float v2 = acc[i][j][2] + b0, v3 = acc[i][j][3] + b1;
            if (BF16OUT) {
                float h0 = __bfloat162float(__float2bfloat16_rn(v0));
                float h1 = __bfloat162float(__float2bfloat16_rn(v1));
                float h2 = __bfloat162float(__float2bfloat16_rn(v2));
                float h3 = __bfloat162float(__float2bfloat16_rn(v3));
                *reinterpret_cast<uint32_t*>(&Ch[(size_t)row * ldc + col])       = pk2(v0, v1);
                *reinterpret_cast<uint32_t*>(&Ch[(size_t)(row + 8) * ldc + col]) = pk2(v2, v3);
                *reinterpret_cast<uint32_t*>(&Cl[(size_t)row * ldc + col])       = pk2(v0 - h0, v1 - h1);
                *reinterpret_cast<uint32_t*>(&Cl[(size_t)(row + 8) * ldc + col]) = pk2(v2 - h2, v3 - h3);
            } else {
                *reinterpret_cast<float2*>(&Cf[(size_t)row * ldc + col])       = make_float2(v0, v1);
                *reinterpret_cast<float2*>(&Cf[(size_t)(row + 8) * ldc + col]) = make_float2(v2, v3);
            }
        }
    }
}

// ---------------------------------------------------------------------------
__global__ void split_kernel(const float4* __restrict__ in,
                             uint2* __restrict__ hi, uint2* __restrict__ lo, int n4)
{
    for (int i = blockIdx.x * blockDim.x + threadIdx.x; i < n4; i += gridDim.x * blockDim.x) {
        float4 v = in[i];
        float h0 = __bfloat162float(__float2bfloat16_rn(v.x));
        float h1 = __bfloat162float(__float2bfloat16_rn(v.y));
        float h2 = __bfloat162float(__float2bfloat16_rn(v.z));
        float h3 = __bfloat162float(__float2bfloat16_rn(v.w));
        hi[i] = make_uint2(pk2(v.x, v.y), pk2(v.z, v.w));
        lo[i] = make_uint2(pk2(v.x - h0, v.y - h1), pk2(v.z - h2, v.w - h3));
    }
}

// ---------------------------------------------------------------------------
__global__ void transpose_hl(const __nv_bfloat16* __restrict__ hi,
                             const __nv_bfloat16* __restrict__ lo,
                             __nv_bfloat16* __restrict__ thi,
                             __nv_bfloat16* __restrict__ tlo)
{
    __shared__ __nv_bfloat16 sm[32][33];
    const size_t zi = (size_t)blockIdx.z * LSEQ * DDIM;
    const int d0 = blockIdx.x * 32, l0 = blockIdx.y * 32;
    const int tx = threadIdx.x, ty = threadIdx.y;

#pragma unroll
    for (int i = 0; i < 4; ++i)
        sm[ty + 8*i][tx] = hi[zi + (size_t)(l0 + ty + 8*i) * DDIM + d0 + tx];
    __syncthreads();
#pragma unroll
    for (int i = 0; i < 4; ++i)
        thi[zi + (size_t)(d0 + ty + 8*i) * LSEQ + l0 + tx] = sm[tx][ty + 8*i];
    __syncthreads();
#pragma unroll
    for (int i = 0; i < 4; ++i)
        sm[ty + 8*i][tx] = lo[zi + (size_t)(l0 + ty + 8*i) * DDIM + d0 + tx];
    __syncthreads();
#pragma unroll
    for (int i = 0; i < 4; ++i)
        tlo[zi + (size_t)(d0 + ty + 8*i) * LSEQ + l0 + tx] = sm[tx][ty + 8*i];
}

// ---------------------------------------------------------------------------
__global__ __launch_bounds__(256) void softmax_rows(const float* __restrict__ S,
                                                    __nv_bfloat16* __restrict__ Ph,
                                                    __nv_bfloat16* __restrict__ Pl)
{
    const size_t row = blockIdx.x;
    const float* p = S + row * (size_t)LSEQ;
    const int tid = threadIdx.x;

    float4 v0 = ((const float4*)p)[tid];
    float4 v1 = ((const float4*)p)[tid + 256];

    __shared__ float red[32];
    const int lane = tid & 31, warp = tid >> 5;

    float m = fmaxf(fmaxf(fmaxf(v0.x, v0.y), fmaxf(v0.z, v0.w)),
                    fmaxf(fmaxf(v1.x, v1.y), fmaxf(v1.z, v1.w)));
#pragma unroll
    for (int o = 16; o > 0; o >>= 1) m = fmaxf(m, __shfl_xor_sync(0xffffffffu, m, o));
    if (lane == 0) red[warp] = m;
    __syncthreads();
    if (warp == 0) {
        float mm = (lane < 8) ? red[lane] : -3.4e38f;
#pragma unroll
        for (int o = 4; o > 0; o >>= 1) mm = fmaxf(mm, __shfl_xor_sync(0xffffffffu, mm, o));
        if (lane == 0) red[0] = mm;
    }
    __syncthreads();
    m = red[0];
    __syncthreads();

    v0.x = __expf(v0.x - m); v0.y = __expf(v0.y - m);
    v0.z = __expf(v0.z - m); v0.w = __expf(v0.w - m);
    v1.x = __expf(v1.x - m); v1.y = __expf(v1.y - m);
    v1.z = __expf(v1.z - m); v1.w = __expf(v1.w - m);
    float s = v0.x + v0.y + v0.z + v0.w + v1.x + v1.y + v1.z + v1.w;
#pragma unroll
    for (int o = 16; o > 0; o >>= 1) s += __shfl_xor_sync(0xffffffffu, s, o);
    if (lane == 0) red[warp] = s;
    __syncthreads();
    if (warp == 0) {
        float ss = (lane < 8) ? red[lane] : 0.f;
#pragma unroll
        for (int o = 4; o > 0; o >>= 1) ss += __shfl_xor_sync(0xffffffffu, ss, o);
        if (lane == 0) red[0] = ss;
    }
    __syncthreads();
    const float inv = 1.0f / red[0];

    float a[8] = {v0.x*inv, v0.y*inv, v0.z*inv, v0.w*inv, v1.x*inv, v1.y*inv, v1.z*inv, v1.w*inv};
    float l[8];
#pragma unroll
    for (int e = 0; e < 8; ++e) {
        float h = __bfloat162float(__float2bfloat16_rn(a[e]));
        l[e] = a[e] - h;
    }
    const size_t o0 = row * (size_t)LSEQ + tid * 4;
    const size_t o1 = row * (size_t)LSEQ + (tid + 256) * 4;
    *reinterpret_cast<uint2*>(&Ph[o0]) = make_uint2(pk2(a[0], a[1]), pk2(a[2], a[3]));
    *reinterpret_cast<uint2*>(&Ph[o1]) = make_uint2(pk2(a[4], a[5]), pk2(a[6], a[7]));
    *reinterpret_cast<uint2*>(&Pl[o0]) = make_uint2(pk2(l[0], l[1]), pk2(l[2], l[3]));
    *reinterpret_cast<uint2*>(&Pl[o1]) = make_uint2(pk2(l[4], l[5]), pk2(l[6], l[7]));
}

// ---------------------------------------------------------------------------
extern "C" void kernel_launch(void* const* d_in, const int* in_sizes, int n_in,
                              void* d_out, int out_size)
{
    const float* x  = (const float*)d_in[0];
    const float* W1 = (const float*)d_in[1];
    const float* b1 = (const float*)d_in[2];
    const float* W2 = (const float*)d_in[3];
    const float* b2 = (const float*)d_in[4];
    float* out = (float*)d_out;

    __nv_bfloat16 *xh, *xl, *w1h, *w1l, *w2h, *w2l, *qh, *ql, *vh, *vl, *vth, *vtl, *phh, *pll;
    float* S;
    cudaGetSymbolAddress((void**)&xh, g_xh);   cudaGetSymbolAddress((void**)&xl, g_xl);
    cudaGetSymbolAddress((void**)&w1h, g_w1h); cudaGetSymbolAddress((void**)&w1l, g_w1l);
    cudaGetSymbolAddress((void**)&w2h, g_w2h); cudaGetSymbolAddress((void**)&w2l, g_w2l);
    cudaGetSymbolAddress((void**)&qh, g_qh);   cudaGetSymbolAddress((void**)&ql, g_ql);
    cudaGetSymbolAddress((void**)&vh, g_vh);   cudaGetSymbolAddress((void**)&vl, g_vl);
    cudaGetSymbolAddress((void**)&vth, g_vth); cudaGetSymbolAddress((void**)&vtl, g_vtl);
    cudaGetSymbolAddress((void**)&phh, g_ph);  cudaGetSymbolAddress((void**)&pll, g_pl);
    cudaGetSymbolAddress((void**)&S, g_S);

    cudaFuncSetAttribute(gemm_hmma<true,  true >, cudaFuncAttributeMaxDynamicSharedMemorySize, SMEM_TOTAL);
    cudaFuncSetAttribute(gemm_hmma<false, false>, cudaFuncAttributeMaxDynamicSharedMemorySize, SMEM_TOTAL);

    const long long LD = (long long)LSEQ * DDIM;
    const long long LL = (long long)LSEQ * LSEQ;

    // 1. split fp32 -> bf16 hi/lo
    split_kernel<<<4096, 256>>>((const float4*)x,  (uint2*)xh,  (uint2*)xl,  8388608 / 4);
    split_kernel<<<1024, 256>>>((const float4*)W1, (uint2*)w1h, (uint2*)w1l, 1048576 / 4);
    split_kernel<<<1024, 256>>>((const float4*)W2, (uint2*)w2h, (uint2*)w2l, 1048576 / 4);

    // 2. Q = x@W1^T + b1 ; V = x@W2^T + b2  (M=8192, N=1024, K=1024)
    {
        dim3 g(DDIM / BN, (BATCH * LSEQ) / BM, 1);
        gemm_hmma<true, true><<<g, 256, SMEM_TOTAL>>>(
            xh, xl, w1h, w1l, b1, nullptr, qh, ql, DDIM, DDIM, DDIM, DDIM, 0, 0, 0);
        gemm_hmma<true, true><<<g, 256, SMEM_TOTAL>>>(
            xh, xl, w2h, w2l, b2, nullptr, vh, vl, DDIM, DDIM, DDIM, DDIM, 0, 0, 0);
    }

    // 3. Vt = V^T per batch (for stage-6 NT form)
    transpose_hl<<<dim3(DDIM / 32, LSEQ / 32, BATCH), dim3(32, 8)>>>(vh, vl, vth, vtl);

    // 4. S[b] = Q[b] @ V[b]^T  (M=2048, N=2048, K=1024)
    {
        dim3 g(LSEQ / BN, LSEQ / BM, BATCH);
        gemm_hmma<false, false><<<g, 256, SMEM_TOTAL>>>(
            qh, ql, vh, vl, nullptr, S, nullptr, nullptr, DDIM, DDIM, DDIM, LSEQ, LD, LD, LL);
    }

    // 5. softmax -> P hi/lo
    softmax_rows<<<BATCH * LSEQ, 256>>>(S, phh, pll);

    // 6. out[b] = P[b] @ Vt[b]^T  (M=2048, N=1024, K=2048)
    {
        dim3 g(DDIM / BN, LSEQ / BM, BATCH);
        gemm_hmma<false, false><<<g, 256, SMEM_TOTAL>>>(
            phh, pll, vth, vtl, nullptr, out, nullptr, nullptr, LSEQ, LSEQ, LSEQ, DDIM, LL, LD, LD);
    }
}

// round 10
// speedup vs baseline: 1.9330x; 1.9330x over previous
#include <cuda_runtime.h>
#include <cuda_fp16.h>
#include <cstdint>

// ============================================================================
// SelfAttention via mma.sync (HMMA) fp16 hi/lo-split GEMMs.
// R9: bf16 -> fp16 (11-bit mantissa). Stages 1-2: 3-pass split (~fp32 acc).
//     Stage 3 (P@V): 1-pass fp16 (errors not amplified by softmax) -> 2/3 of
//     stage-3 MMA work removed. Effective MMA work 309 -> 240 GF.
// B=4, L=2048, D=1024.
// ============================================================================

#define BATCH 4
#define LSEQ  2048
#define DDIM  1024

#define BM 128
#define BN 128
#define BK 32

// ---- scratch ---------------------------------------------------------------
__device__ __half g_xh[8388608],  g_xl[8388608];
__device__ __half g_w1h[1048576], g_w1l[1048576];
__device__ __half g_w2h[1048576], g_w2l[1048576];
__device__ __half g_qh[8388608],  g_ql[8388608];
__device__ __half g_vh[8388608],  g_vl[8388608];
__device__ __half g_vth[8388608];                 // V^T hi only (stage-3 1-pass)
__device__ float  g_S[16777216];
__device__ __half g_ph[16777216];                  // softmax P (fp16, 1-pass)

// ---- helpers ---------------------------------------------------------------
__device__ __forceinline__ uint32_t smem_u32(const void* p) {
    uint32_t a;
    asm("{ .reg .u64 t; cvta.to.shared.u64 t, %1; cvt.u32.u64 %0, t; }" : "=r"(a) : "l"(p));
    return a;
}
__device__ __forceinline__ void cp16(uint32_t dst, const void* src) {
    asm volatile("cp.async.cg.shared.global [%0], [%1], 16;" :: "r"(dst), "l"(src));
}
__device__ __forceinline__ void cp_commit() { asm volatile("cp.async.commit_group;" ::: "memory"); }
#define CP_WAIT1 asm volatile("cp.async.wait_group 1;" ::: "memory")
#define CP_WAIT0 asm volatile("cp.async.wait_group 0;" ::: "memory")

__device__ __forceinline__ void ldsm4(uint32_t& r0, uint32_t& r1, uint32_t& r2, uint32_t& r3,
                                      uint32_t addr) {
    asm volatile("ldmatrix.sync.aligned.m8n8.x4.shared.b16 {%0,%1,%2,%3}, [%4];"
                 : "=r"(r0), "=r"(r1), "=r"(r2), "=r"(r3) : "r"(addr));
}
__device__ __forceinline__ void mma16816(float* c, const uint32_t* a, const uint32_t* b) {
    asm volatile(
        "mma.sync.aligned.m16n8k16.row.col.f32.f16.f16.f32 "
        "{%0,%1,%2,%3}, {%4,%5,%6,%7}, {%8,%9}, {%0,%1,%2,%3};"
        : "+f"(c[0]), "+f"(c[1]), "+f"(c[2]), "+f"(c[3])
        : "r"(a[0]), "r"(a[1]), "r"(a[2]), "r"(a[3]), "r"(b[0]), "r"(b[1]));
}
__device__ __forceinline__ uint32_t pk2h(float a, float b) {
    __half2 t = __floats2half2_rn(a, b);
    return *reinterpret_cast<uint32_t*>(&t);
}

// SMEM layout (bytes): 4 tiles of 128 rows x 80 B = 10240 B each
#define T_AH 0
#define T_AL 10240
#define T_BH 20480
#define T_BL 30720
#define STAGE 40960
#define SMEM_TOTAL (2 * STAGE)    // 81920

// ============================================================================
// C[M,N] = A[M,K] * B[N,K]^T  (both K-contiguous).
// NPASS=3: hi/lo split, 3 MMA passes (~fp32). NPASS=1: plain fp16 single pass.
// grid (N/BN, M/BM, batch), 256 threads (8 warps, warp tile 64x32).
// ============================================================================
template <bool BIAS, bool HOUT, int NPASS>
__global__ __launch_bounds__(256, 2) void gemm_hmma(
    const __half* __restrict__ Ah, const __half* __restrict__ Al,
    const __half* __restrict__ Bh, const __half* __restrict__ Bl,
    const float* __restrict__ bias,
    float* __restrict__ Cf, __half* __restrict__ Ch, __half* __restrict__ Cl,
    int K, int lda, int ldb, int ldc,
    long long sA, long long sB, long long sC)
{
    extern __shared__ char smem[];
    const uint32_t sb = smem_u32(smem);

    const int tid = threadIdx.x, wid = tid >> 5, lane = tid & 31;
    const int wy = wid >> 2, wx = wid & 3;           // warp grid 2 x 4
    const int m0 = blockIdx.y * BM, n0 = blockIdx.x * BN;
    const long long z = blockIdx.z;
    Ah += z * sA; Bh += z * sB;
    if (NPASS == 3) { Al += z * sA; Bl += z * sB; }
    if (HOUT) { Ch += z * sC; Cl += z * sC; } else { Cf += z * sC; }

    // global->smem mapping: 512 16B segs per tile (128 rows x 4)
    const int grow = tid >> 2;
    const int gseg = tid & 3;

    float acc[4][4][4];
#pragma unroll
    for (int i = 0; i < 4; ++i)
#pragma unroll
        for (int j = 0; j < 4; ++j)
#pragma unroll
            for (int e = 0; e < 4; ++e) acc[i][j][e] = 0.f;

    const int nk = K / BK;

    auto load_chunk = [&](int t, int b) {
        const uint32_t st = sb + b * STAGE;
        const int k0 = t * BK;
#pragma unroll
        for (int h = 0; h < 2; ++h) {
            const int row = grow + h * 64;
            const uint32_t d = (uint32_t)(row * 80 + gseg * 16);
            const size_t ga = (size_t)(m0 + row) * lda + k0 + gseg * 8;
            const size_t gb = (size_t)(n0 + row) * ldb + k0 + gseg * 8;
            cp16(st + T_AH + d, Ah + ga);
            cp16(st + T_BH + d, Bh + gb);
            if (NPASS == 3) {
                cp16(st + T_AL + d, Al + ga);
                cp16(st + T_BL + d, Bl + gb);
            }
        }
    };

    load_chunk(0, 0);
    cp_commit();

    for (int t = 0; t < nk; ++t) {
        const int buf = t & 1;
        if (t + 1 < nk) { load_chunk(t + 1, buf ^ 1); cp_commit(); CP_WAIT1; }
        else            { CP_WAIT0; }
        __syncthreads();

        const uint32_t st = sb + buf * STAGE;
        const int lr = lane & 15, lc = lane >> 4;
#pragma unroll
        for (int ks = 0; ks < 2; ++ks) {
            const uint32_t acol = (uint32_t)(ks * 32 + lc * 16);
            const uint32_t ab = st + T_AH + (uint32_t)((wy * 64 + lr) * 80) + acol;
            const uint32_t bb = st + T_BH + (uint32_t)((wx * 32 + lr) * 80) + acol;

            uint32_t ah[4][4], bh[4][2];
#pragma unroll
            for (int i = 0; i < 4; ++i) {
                const uint32_t ad = ab + (uint32_t)(i * 16 * 80);
                ldsm4(ah[i][0], ah[i][1], ah[i][2], ah[i][3], ad);
            }
#pragma unroll
            for (int j = 0; j < 2; ++j) {
                const uint32_t bd = bb + (uint32_t)(j * 16 * 80);
                uint32_t r0, r1, r2, r3;
                ldsm4(r0, r1, r2, r3, bd);
                bh[2*j][0] = r0; bh[2*j][1] = r2; bh[2*j+1][0] = r1; bh[2*j+1][1] = r3;
            }

#pragma unroll
            for (int i = 0; i < 4; ++i)
#pragma unroll
                for (int j = 0; j < 4; ++j)
                    mma16816(acc[i][j], ah[i], bh[j]);

            if (NPASS == 3) {
                uint32_t al[4][4], bl[4][2];
#pragma unroll
                for (int i = 0; i < 4; ++i) {
                    const uint32_t ad = ab + (uint32_t)(i * 16 * 80) + (T_AL - T_AH);
                    ldsm4(al[i][0], al[i][1], al[i][2], al[i][3], ad);
                }
#pragma unroll
                for (int j = 0; j < 2; ++j) {
                    const uint32_t bd = bb + (uint32_t)(j * 16 * 80) + (T_BL - T_BH);
                    uint32_t r0, r1, r2, r3;
                    ldsm4(r0, r1, r2, r3, bd);
                    bl[2*j][0] = r0; bl[2*j][1] = r2; bl[2*j+1][0] = r1; bl[2*j+1][1] = r3;
                }
                // RAW distance 16 between touches of the same acc quad
#pragma unroll
                for (int i = 0; i < 4; ++i)
#pragma unroll
                    for (int j = 0; j < 4; ++j)
                        mma16816(acc[i][j], ah[i], bl[j]);
#pragma unroll
                for (int i = 0; i < 4; ++i)
#pragma unroll
                    for (int j = 0; j < 4; ++j)
                        mma16816(acc[i][j], al[i], bh[j]);
            }
        }
        __syncthreads();
    }

    // ---- epilogue ----
    const int rbase = m0 + wy * 64 + (lane >> 2);
    const int cbase = n0 + wx * 32 + (lane & 3) * 2;
#pragma unroll
    for (int j = 0; j < 4; ++j) {
        const int col = cbase + j * 8;
        float b0 = 0.f, b1 = 0.f;
        if (BIAS) { b0 = __ldg(&bias[col]); b1 = __ldg(&bias[col + 1]); }
#pragma unroll
        for (int i = 0; i < 4; ++i) {
            const int row = rbase + i * 16;
            float v0 = acc[i][j][0] + b0, v1 = acc[i][j][1] + b1;
            float v2 = acc[i][j][2] + b0, v3 = acc[i][j][3] + b1;
            if (HOUT) {
                float h0 = __half2float(__float2half_rn(v0));
                float h1 = __half2float(__float2half_rn(v1));
                float h2 = __half2float(__float2half_rn(v2));
                float h3 = __half2float(__float2half_rn(v3));
                *reinterpret_cast<uint32_t*>(&Ch[(size_t)row * ldc + col])       = pk2h(v0, v1);
                *reinterpret_cast<uint32_t*>(&Ch[(size_t)(row + 8) * ldc + col]) = pk2h(v2, v3);
                *reinterpret_cast<uint32_t*>(&Cl[(size_t)row * ldc + col])       = pk2h(v0 - h0, v1 - h1);
                *reinterpret_cast<uint32_t*>(&Cl[(size_t)(row + 8) * ldc + col]) = pk2h(v2 - h2, v3 - h3);
            } else {
                *reinterpret_cast<float2*>(&Cf[(size_t)row * ldc + col])       = make_float2(v0, v1);
                *reinterpret_cast<float2*>(&Cf[(size_t)(row + 8) * ldc + col]) = make_float2(v2, v3);
            }
        }
    }
}

// ---------------------------------------------------------------------------
// fp32 -> fp16 hi/lo split
// ---------------------------------------------------------------------------
__global__ void split_kernel(const float4* __restrict__ in,
                             uint2* __restrict__ hi, uint2* __restrict__ lo, int n4)
{
    for (int i = blockIdx.x * blockDim.x + threadIdx.x; i < n4; i += gridDim.x * blockDim.x) {
        float4 v = in[i];
        float h0 = __half2float(__float2half_rn(v.x));
        float h1 = __half2float(__float2half_rn(v.y));
        float h2 = __half2float(__float2half_rn(v.z));
        float h3 = __half2float(__float2half_rn(v.w));
        hi[i] = make_uint2(pk2h(v.x, v.y), pk2h(v.z, v.w));
        lo[i] = make_uint2(pk2h(v.x - h0, v.y - h1), pk2h(v.z - h2, v.w - h3));
    }
}

// ---------------------------------------------------------------------------
// V[L,D] -> Vt[D,L] (hi only), per batch
// ---------------------------------------------------------------------------
__global__ void transpose_h(const __half* __restrict__ hi, __half* __restrict__ thi)
{
    __shared__ __half sm[32][33];
    const size_t zi = (size_t)blockIdx.z * LSEQ * DDIM;
    const int d0 = blockIdx.x * 32, l0 = blockIdx.y * 32;
    const int tx = threadIdx.x, ty = threadIdx.y;

#pragma unroll
    for (int i = 0; i < 4; ++i)
        sm[ty + 8*i][tx] = hi[zi + (size_t)(l0 + ty + 8*i) * DDIM + d0 + tx];
    __syncthreads();
#pragma unroll
    for (int i = 0; i < 4; ++i)
        thi[zi + (size_t)(d0 + ty + 8*i) * LSEQ + l0 + tx] = sm[tx][ty + 8*i];
}

// ---------------------------------------------------------------------------
// Row softmax (2048 wide) -> P fp16
// ---------------------------------------------------------------------------
__global__ __launch_bounds__(256) void softmax_rows(const float* __restrict__ S,
                                                    __half* __restrict__ Ph)
{
    const size_t row = blockIdx.x;
    const float* p = S + row * (size_t)LSEQ;
    const int tid = threadIdx.x;

    float4 v0 = ((const float4*)p)[tid];
    float4 v1 = ((const float4*)p)[tid + 256];

    __shared__ float red[32];
    const int lane = tid & 31, warp = tid >> 5;

    float m = fmaxf(fmaxf(fmaxf(v0.x, v0.y), fmaxf(v0.z, v0.w)),
                    fmaxf(fmaxf(v1.x, v1.y), fmaxf(v1.z, v1.w)));
#pragma unroll
    for (int o = 16; o > 0; o >>= 1) m = fmaxf(m, __shfl_xor_sync(0xffffffffu, m, o));
    if (lane == 0) red[warp] = m;
    __syncthreads();
    if (warp == 0) {
        float mm = (lane < 8) ? red[lane] : -3.4e38f;
#pragma unroll
        for (int o = 4; o > 0; o >>= 1) mm = fmaxf(mm, __shfl_xor_sync(0xffffffffu, mm, o));
        if (lane == 0) red[0] = mm;
    }
    __syncthreads();
    m = red[0];
    __syncthreads();

    v0.x = __expf(v0.x - m); v0.y = __expf(v0.y - m);
    v0.z = __expf(v0.z - m); v0.w = __expf(v0.w - m);
    v1.x = __expf(v1.x - m); v1.y = __expf(v1.y - m);
    v1.z = __expf(v1.z - m); v1.w = __expf(v1.w - m);
    float s = v0.x + v0.y + v0.z + v0.w + v1.x + v1.y + v1.z + v1.w;
#pragma unroll
    for (int o = 16; o > 0; o >>= 1) s += __shfl_xor_sync(0xffffffffu, s, o);
    if (lane == 0) red[warp] = s;
    __syncthreads();
    if (warp == 0) {
        float ss = (lane < 8) ? red[lane] : 0.f;
#pragma unroll
        for (int o = 4; o > 0; o >>= 1) ss += __shfl_xor_sync(0xffffffffu, ss, o);
        if (lane == 0) red[0] = ss;
    }
    __syncthreads();
    const float inv = 1.0f / red[0];

    float a[8] = {v0.x*inv, v0.y*inv, v0.z*inv, v0.w*inv, v1.x*inv, v1.y*inv, v1.z*inv, v1.w*inv};
    const size_t o0 = row * (size_t)LSEQ + tid * 4;
    const size_t o1 = row * (size_t)LSEQ + (tid + 256) * 4;
    *reinterpret_cast<uint2*>(&Ph[o0]) = make_uint2(pk2h(a[0], a[1]), pk2h(a[2], a[3]));
    *reinterpret_cast<uint2*>(&Ph[o1]) = make_uint2(pk2h(a[4], a[5]), pk2h(a[6], a[7]));
}

// ---------------------------------------------------------------------------
extern "C" void kernel_launch(void* const* d_in, const int* in_sizes, int n_in,
                              void* d_out, int out_size)
{
    const float* x  = (const float*)d_in[0];
    const float* W1 = (const float*)d_in[1];
    const float* b1 = (const float*)d_in[2];
    const float* W2 = (const float*)d_in[3];
    const float* b2 = (const float*)d_in[4];
    float* out = (float*)d_out;

    __half *xh, *xl, *w1h, *w1l, *w2h, *w2l, *qh, *ql, *vh, *vl, *vth, *phh;
    float* S;
    cudaGetSymbolAddress((void**)&xh, g_xh);   cudaGetSymbolAddress((void**)&xl, g_xl);
    cudaGetSymbolAddress((void**)&w1h, g_w1h); cudaGetSymbolAddress((void**)&w1l, g_w1l);
    cudaGetSymbolAddress((void**)&w2h, g_w2h); cudaGetSymbolAddress((void**)&w2l, g_w2l);
    cudaGetSymbolAddress((void**)&qh, g_qh);   cudaGetSymbolAddress((void**)&ql, g_ql);
    cudaGetSymbolAddress((void**)&vh, g_vh);   cudaGetSymbolAddress((void**)&vl, g_vl);
    cudaGetSymbolAddress((void**)&vth, g_vth);
    cudaGetSymbolAddress((void**)&phh, g_ph);
    cudaGetSymbolAddress((void**)&S, g_S);

    cudaFuncSetAttribute(gemm_hmma<true,  true,  3>, cudaFuncAttributeMaxDynamicSharedMemorySize, SMEM_TOTAL);
    cudaFuncSetAttribute(gemm_hmma<false, false, 3>, cudaFuncAttributeMaxDynamicSharedMemorySize, SMEM_TOTAL);
    cudaFuncSetAttribute(gemm_hmma<false, false, 1>, cudaFuncAttributeMaxDynamicSharedMemorySize, SMEM_TOTAL);

    const long long LD = (long long)LSEQ * DDIM;
    const long long LL = (long long)LSEQ * LSEQ;

    // 1. split fp32 -> fp16 hi/lo
    split_kernel<<<4096, 256>>>((const float4*)x,  (uint2*)xh,  (uint2*)xl,  8388608 / 4);
    split_kernel<<<1024, 256>>>((const float4*)W1, (uint2*)w1h, (uint2*)w1l, 1048576 / 4);
    split_kernel<<<1024, 256>>>((const float4*)W2, (uint2*)w2h, (uint2*)w2l, 1048576 / 4);

    // 2. Q = x@W1^T + b1 ; V = x@W2^T + b2  (M=8192, N=1024, K=1024, 3-pass)
    {
        dim3 g(DDIM / BN, (BATCH * LSEQ) / BM, 1);
        gemm_hmma<true, true, 3><<<g, 256, SMEM_TOTAL>>>(
            xh, xl, w1h, w1l, b1, nullptr, qh, ql, DDIM, DDIM, DDIM, DDIM, 0, 0, 0);
        gemm_hmma<true, true, 3><<<g, 256, SMEM_TOTAL>>>(
            xh, xl, w2h, w2l, b2, nullptr, vh, vl, DDIM, DDIM, DDIM, DDIM, 0, 0, 0);
    }

    // 3. Vt = V^T per batch (hi only, for 1-pass stage 6)
    transpose_h<<<dim3(DDIM / 32, LSEQ / 32, BATCH), dim3(32, 8)>>>(vh, vth);

    // 4. S[b] = Q[b] @ V[b]^T  (M=2048, N=2048, K=1024, 3-pass)
    {
        dim3 g(LSEQ / BN, LSEQ / BM, BATCH);
        gemm_hmma<false, false, 3><<<g, 256, SMEM_TOTAL>>>(
            qh, ql, vh, vl, nullptr, S, nullptr, nullptr, DDIM, DDIM, DDIM, LSEQ, LD, LD, LL);
    }

    // 5. softmax -> P fp16
    softmax_rows<<<BATCH * LSEQ, 256>>>(S, phh);

    // 6. out[b] = P[b] @ Vt[b]^T  (M=2048, N=1024, K=2048, 1-pass fp16)
    {
        dim3 g(DDIM / BN, LSEQ / BM, BATCH);
        gemm_hmma<false, false, 1><<<g, 256, SMEM_TOTAL>>>(
            phh, phh, vth, vth, nullptr, out, nullptr, nullptr, LSEQ, LSEQ, LSEQ, DDIM, LL, LD, LD);
    }
}